// round 1
// baseline (speedup 1.0000x reference)
#include <cuda_runtime.h>

// DynamicUpsamplingFilter:
//   x:       (1, 3, 25, 128, 128) float32          -> d_in[0]
//   filters: (1, 25, 16, 25, 128, 128) float32     -> d_in[1]
//   out:     (1, 48, 25, 128, 128) float32
// out[c*16+u, t, h, w] = sum_{a,b} x[c, t, h+a-2, w+b-2] * filters[a*5+b, u, t, h, w]
// (zero padding outside [0,128) in h and w)

#define T_DIM 25
#define H_DIM 128
#define W_DIM 128
#define HW    (H_DIM * W_DIM)       // 16384
#define THW   (T_DIM * HW)          // 409600
#define C_IN  3
#define KH    5
#define KW    5
#define NK    (KH * KW)             // 25
#define UPSQ  16

__global__ __launch_bounds__(W_DIM, 5)
void duf_kernel(const float* __restrict__ x,
                const float* __restrict__ f,
                float* __restrict__ out)
{
    const int w = threadIdx.x;           // 0..127
    const int h = blockIdx.x & (H_DIM - 1);
    const int t = blockIdx.x >> 7;       // blockIdx.x / 128

    // x patch tile: 3 channels x 5 rows x (128 + 4) cols, zero halo in w
    __shared__ float sx[C_IN][KH][W_DIM + 4];

    // zero the 2-wide w-halos (block spans the full row, so halo is always OOB -> 0)
    if (w < 2) {
        #pragma unroll
        for (int c = 0; c < C_IN; c++)
            #pragma unroll
            for (int a = 0; a < KH; a++) {
                sx[c][a][w] = 0.0f;
                sx[c][a][W_DIM + 2 + w] = 0.0f;
            }
    }

    // stage x rows h-2..h+2 for all 3 channels (zero outside [0,H))
    #pragma unroll
    for (int c = 0; c < C_IN; c++) {
        #pragma unroll
        for (int a = 0; a < KH; a++) {
            const int hh = h + a - 2;
            float v = 0.0f;
            if (hh >= 0 && hh < H_DIM)
                v = __ldg(&x[c * THW + t * HW + hh * W_DIM + w]);
            sx[c][a][w + 2] = v;
        }
    }
    __syncthreads();

    const int pix = t * HW + h * W_DIM + w;
    const float* fp = f + pix;

    float acc[C_IN * UPSQ];
    #pragma unroll
    for (int i = 0; i < C_IN * UPSQ; i++) acc[i] = 0.0f;

    // k outer (25 iters, not fully unrolled -> small I$ footprint),
    // u inner fully unrolled (16 independent DRAM loads in flight)
    #pragma unroll 1
    for (int k = 0; k < NK; k++) {
        const int a = k / KW;
        const int b = k - a * KW;
        const float p0 = sx[0][a][w + b];
        const float p1 = sx[1][a][w + b];
        const float p2 = sx[2][a][w + b];
        const float* fk = fp + (size_t)k * (UPSQ * THW);
        #pragma unroll
        for (int u = 0; u < UPSQ; u++) {
            const float fv = __ldg(&fk[(size_t)u * THW]);
            acc[u]             = fmaf(p0, fv, acc[u]);
            acc[UPSQ + u]      = fmaf(p1, fv, acc[UPSQ + u]);
            acc[2 * UPSQ + u]  = fmaf(p2, fv, acc[2 * UPSQ + u]);
        }
    }

    // out[(c*16+u)*THW + pix], coalesced across w
    #pragma unroll
    for (int i = 0; i < C_IN * UPSQ; i++)
        out[(size_t)i * THW + pix] = acc[i];
}

extern "C" void kernel_launch(void* const* d_in, const int* in_sizes, int n_in,
                              void* d_out, int out_size)
{
    const float* x = (const float*)d_in[0];
    const float* f = (const float*)d_in[1];
    float* out = (float*)d_out;

    dim3 grid(T_DIM * H_DIM);   // 3200 blocks: one per (t, h) row
    dim3 block(W_DIM);          // 128 threads: one per w
    duf_kernel<<<grid, block>>>(x, f, out);
}